// round 17
// baseline (speedup 1.0000x reference)
#include <cuda_runtime.h>

// Batched DLT: 262144 independent 8x8 systems, h = pinv(A)@b == solve(A,b).
// R15: packed f32x2 ILP-2. Two systems per thread, with the data-parallel
// front (pairwise dets, null vector w, b-dots, Kahan det2/Cramer, g-RHS)
// executed in Blackwell's dual-lane f32x2 ISA via inline PTX — one packed
// instruction does both systems' op (ptxas never auto-fuses; R11 proved
// float2 source compiles to 2x scalar). Halves front instr count AND front
// critical path vs R14's sequential 2-system structure. Scalar per lane:
// converts, exact int64 normal-matrix dots + hi/lo splits, rcp, pivot+tail.
// All packed lanes are IEEE fp32 ops => R14's exactness proofs carry over.

typedef unsigned long long u64;

__device__ __forceinline__ u64 pk(float lo, float hi) {
    u64 r; asm("mov.b64 %0,{%1,%2};" : "=l"(r) : "f"(lo), "f"(hi)); return r;
}
__device__ __forceinline__ void upk(u64 v, float& lo, float& hi) {
    asm("mov.b64 {%0,%1},%2;" : "=f"(lo), "=f"(hi) : "l"(v));
}
__device__ __forceinline__ u64 add2(u64 a, u64 b) {
    u64 d; asm("add.rn.f32x2 %0,%1,%2;" : "=l"(d) : "l"(a), "l"(b)); return d;
}
__device__ __forceinline__ u64 mul2(u64 a, u64 b) {
    u64 d; asm("mul.rn.f32x2 %0,%1,%2;" : "=l"(d) : "l"(a), "l"(b)); return d;
}
__device__ __forceinline__ u64 fma2(u64 a, u64 b, u64 c) {
    u64 d; asm("fma.rn.f32x2 %0,%1,%2,%3;" : "=l"(d) : "l"(a), "l"(b), "l"(c)); return d;
}
static const u64 M1 = 0xBF800000BF800000ULL;   // packed (-1.f, -1.f)
__device__ __forceinline__ u64 neg2(u64 a) { return mul2(a, M1); }   // exact
__device__ __forceinline__ u64 sub2(u64 a, u64 b) { return add2(a, neg2(b)); }
// a*b + c*d packed (exact when products are integers < 2^24)
__device__ __forceinline__ u64 det2p(u64 a, u64 b, u64 c, u64 d) {
    return fma2(a, b, mul2(c, d));
}
// Kahan a*b - c*e packed (~1.5 ulp)
__device__ __forceinline__ u64 kdet2p(u64 a, u64 b, u64 c, u64 e) {
    u64 w  = mul2(c, e);
    u64 nw = neg2(w);
    u64 e1 = fma2(c, e, nw);
    u64 f  = fma2(a, b, nw);
    return sub2(f, e1);
}

struct hl { float h, l; };
__device__ __forceinline__ hl split_ll(long long v) {   // exact for |v|<2^48
    float h = (float)v;
    float l = (float)(v - (long long)h);
    return hl{h, l};
}

// Per-system tail: pivot + shared 3x3 adjugate solve; writes 9 floats to o.
__device__ __forceinline__ void tail_one(
    float tu0, float tv0, float tu1, float tv1,
    float tu2, float tv2, float tu3, float tv3,
    float w0f, float w1f, float w2f, float w3f,
    float gx0, float gx1, float gx2, float gx3,
    float gy0, float gy1, float gy2, float gy3,
    float z1, float z2, float* __restrict__ o)
{
    float aw0 = fabsf(w0f), aw1 = fabsf(w1f), aw2 = fabsf(w2f), aw3 = fabsf(w3f);
    int k = 0; float awm = aw0;
    if (aw1 > awm) { k = 1; awm = aw1; }
    if (aw2 > awm) { k = 2; awm = aw2; }
    if (aw3 > awm) { k = 3; awm = aw3; }
    bool c0 = (k == 0), c1 = (k <= 1), c2 = (k <= 2);

    float A1 = c0 ? tu1 : tu0,  B1 = c0 ? tv1 : tv0;
    float A2 = c1 ? tu2 : tu1,  B2 = c1 ? tv2 : tv1;
    float A3 = c2 ? tu3 : tu2,  B3 = c2 ? tv3 : tv2;
    float G1x = c0 ? gx1 : gx0, G1y = c0 ? gy1 : gy0;
    float G2x = c1 ? gx2 : gx1, G2y = c1 ? gy2 : gy1;
    float G3x = c2 ? gx3 : gx2, G3y = c2 ? gy3 : gy2;

    // 3x3 adjugate — exact fp32 (integer cofactors < 2^23).
    float e12 = fmaf(A1, B2, -(A2 * B1));
    float e23 = fmaf(A2, B3, -(A3 * B2));
    float e31 = fmaf(A3, B1, -(A1 * B3));
    float det3 = e12 + e23 + e31;
    float inv3 = __frcp_rn(det3);

    float r11 = B2 - B3, r12 = B3 - B1, r13 = B1 - B2;
    float r21 = A3 - A2, r22 = A1 - A3, r23 = A2 - A1;

    o[0] = fmaf(r11, G1x, fmaf(r12, G2x, r13 * G3x)) * inv3;
    o[1] = fmaf(r21, G1x, fmaf(r22, G2x, r23 * G3x)) * inv3;
    o[2] = fmaf(e23, G1x, fmaf(e31, G2x, e12 * G3x)) * inv3;
    o[3] = fmaf(r11, G1y, fmaf(r12, G2y, r13 * G3y)) * inv3;
    o[4] = fmaf(r21, G1y, fmaf(r22, G2y, r23 * G3y)) * inv3;
    o[5] = fmaf(e23, G1y, fmaf(e31, G2y, e12 * G3y)) * inv3;
    o[6] = z1;
    o[7] = z2;
    o[8] = 1.0f;
}

__device__ __forceinline__ void flush_tile(float* __restrict__ out,
                                           const float* __restrict__ srow,
                                           size_t base, int lane,
                                           bool full, size_t lim)
{
    if (full) {
        const float4* s4 = reinterpret_cast<const float4*>(srow);
        float4* o4 = reinterpret_cast<float4*>(out + base);
        o4[lane]      = s4[lane];
        o4[lane + 32] = s4[lane + 32];
        if (lane < 8) o4[lane + 64] = s4[lane + 64];
    } else {
        #pragma unroll
        for (int c = 0; c < 9; c++) {
            size_t idx = base + lane + 32 * c;
            if (idx < lim) out[idx] = srow[lane + 32 * c];
        }
    }
}

__global__ __launch_bounds__(128, 5)
void dlt_kernel(const float* __restrict__ x, const float* __restrict__ xp,
                float* __restrict__ out, int B, int T)
{
    __shared__ __align__(16) float stage[4][288];
    int t = blockIdx.x * blockDim.x + threadIdx.x;
    int lane = threadIdx.x & 31;
    int warp = threadIdx.x >> 5;
    float* srow = stage[warp];

    int j0 = t < T ? t : (T - 1);
    int j1 = j0 + T;
    int j1c = (j1 < B) ? j1 : j0;

    const float4* xv  = reinterpret_cast<const float4*>(x);
    const float4* xpv = reinterpret_cast<const float4*>(xp);

    float4 a0A = xv[2*j0],  a1A = xv[2*j0 + 1];
    float4 p0A = xpv[2*j0], p1A = xpv[2*j0 + 1];
    float4 a0B = xv[2*j1c], a1B = xv[2*j1c + 1];
    float4 p0B = xpv[2*j1c], p1B = xpv[2*j1c + 1];

    // ---------- scalar per-lane prep (converts / RZ products) ----------
    // trunc of raw coords — exact.
    float tu0A = truncf(a0A.x), tv0A = truncf(a0A.y), tu1A = truncf(a0A.z), tv1A = truncf(a0A.w);
    float tu2A = truncf(a1A.x), tv2A = truncf(a1A.y), tu3A = truncf(a1A.z), tv3A = truncf(a1A.w);
    float tu0B = truncf(a0B.x), tv0B = truncf(a0B.y), tu1B = truncf(a0B.z), tv1B = truncf(a0B.w);
    float tu2B = truncf(a1B.x), tv2B = truncf(a1B.y), tu3B = truncf(a1B.z), tv3B = truncf(a1B.w);

    // exact trunc(a*b): RZ product cannot cross the integer at/below |a*b|.
    float rcu0A = __fmul_rz(p0A.y, a0A.x), rcu1A = __fmul_rz(p0A.w, a0A.z);
    float rcu2A = __fmul_rz(p1A.y, a1A.x), rcu3A = __fmul_rz(p1A.w, a1A.z);
    float rcv0A = __fmul_rz(p0A.y, a0A.y), rcv1A = __fmul_rz(p0A.w, a0A.w);
    float rcv2A = __fmul_rz(p1A.y, a1A.y), rcv3A = __fmul_rz(p1A.w, a1A.w);
    float rdu0A = __fmul_rz(p0A.x, a0A.x), rdu1A = __fmul_rz(p0A.z, a0A.z);
    float rdu2A = __fmul_rz(p1A.x, a1A.x), rdu3A = __fmul_rz(p1A.z, a1A.z);
    float rdv0A = __fmul_rz(p0A.x, a0A.y), rdv1A = __fmul_rz(p0A.z, a0A.w);
    float rdv2A = __fmul_rz(p1A.x, a1A.y), rdv3A = __fmul_rz(p1A.z, a1A.w);
    float rcu0B = __fmul_rz(p0B.y, a0B.x), rcu1B = __fmul_rz(p0B.w, a0B.z);
    float rcu2B = __fmul_rz(p1B.y, a1B.x), rcu3B = __fmul_rz(p1B.w, a1B.z);
    float rcv0B = __fmul_rz(p0B.y, a0B.y), rcv1B = __fmul_rz(p0B.w, a0B.w);
    float rcv2B = __fmul_rz(p1B.y, a1B.y), rcv3B = __fmul_rz(p1B.w, a1B.w);
    float rdu0B = __fmul_rz(p0B.x, a0B.x), rdu1B = __fmul_rz(p0B.z, a0B.z);
    float rdu2B = __fmul_rz(p1B.x, a1B.x), rdu3B = __fmul_rz(p1B.z, a1B.z);
    float rdv0B = __fmul_rz(p0B.x, a0B.y), rdv1B = __fmul_rz(p0B.z, a0B.w);
    float rdv2B = __fmul_rz(p1B.x, a1B.y), rdv3B = __fmul_rz(p1B.z, a1B.w);

    // ---------- packed front: lane0 = system A, lane1 = system B ----------
    u64 tu0 = pk(tu0A, tu0B), tv0 = pk(tv0A, tv0B);
    u64 tu1 = pk(tu1A, tu1B), tv1 = pk(tv1A, tv1B);
    u64 tu2 = pk(tu2A, tu2B), tv2 = pk(tv2A, tv2B);
    u64 tu3 = pk(tu3A, tu3B), tv3 = pk(tv3A, tv3B);
    u64 up0 = pk(p0A.x, p0B.x), vp0 = pk(p0A.y, p0B.y);
    u64 up1 = pk(p0A.z, p0B.z), vp1 = pk(p0A.w, p0B.w);
    u64 up2 = pk(p1A.x, p1B.x), vp2 = pk(p1A.y, p1B.y);
    u64 up3 = pk(p1A.z, p1B.z), vp3 = pk(p1A.w, p1B.w);

    // Pairwise dets + w — exact packed fp32 (integer results < 2^24).
    u64 ntv0 = neg2(tv0), ntv1 = neg2(tv1), ntv2 = neg2(tv2);
    u64 D01 = det2p(tu0, tv1, tu1, ntv0);
    u64 D02 = det2p(tu0, tv2, tu2, ntv0);
    u64 D03 = det2p(tu0, tv3, tu3, ntv0);
    u64 D12 = det2p(tu1, tv2, tu2, ntv1);
    u64 D13 = det2p(tu1, tv3, tu3, ntv1);
    u64 D23 = det2p(tu2, tv3, tu3, ntv2);
    u64 w0p = sub2(add2(D12, D23), D13);
    u64 w1p = sub2(sub2(D03, D02), D23);
    u64 w2p = sub2(add2(D01, D13), D03);
    u64 w3p = sub2(sub2(D02, D01), D12);

    // b-dots packed.
    u64 b1p = neg2(fma2(w0p, vp0, fma2(w1p, vp1, fma2(w2p, vp2, mul2(w3p, vp3)))));
    u64 b2p = neg2(fma2(w0p, up0, fma2(w1p, up1, fma2(w2p, up2, mul2(w3p, up3)))));

    // ---------- scalar exact int64 normal-matrix dots + splits ----------
    float w0A, w0B, w1A, w1B, w2A, w2B, w3A, w3B;
    upk(w0p, w0A, w0B); upk(w1p, w1A, w1B);
    upk(w2p, w2A, w2B); upk(w3p, w3A, w3B);
    int iw0A = (int)w0A, iw1A = (int)w1A, iw2A = (int)w2A, iw3A = (int)w3A;
    int iw0B = (int)w0B, iw1B = (int)w1B, iw2B = (int)w2B, iw3B = (int)w3B;

    int cu0A=(int)rcu0A, cu1A=(int)rcu1A, cu2A=(int)rcu2A, cu3A=(int)rcu3A;
    int cv0A=(int)rcv0A, cv1A=(int)rcv1A, cv2A=(int)rcv2A, cv3A=(int)rcv3A;
    int du0A=(int)rdu0A, du1A=(int)rdu1A, du2A=(int)rdu2A, du3A=(int)rdu3A;
    int dv0A=(int)rdv0A, dv1A=(int)rdv1A, dv2A=(int)rdv2A, dv3A=(int)rdv3A;
    int cu0B=(int)rcu0B, cu1B=(int)rcu1B, cu2B=(int)rcu2B, cu3B=(int)rcu3B;
    int cv0B=(int)rcv0B, cv1B=(int)rcv1B, cv2B=(int)rcv2B, cv3B=(int)rcv3B;
    int du0B=(int)rdu0B, du1B=(int)rdu1B, du2B=(int)rdu2B, du3B=(int)rdu3B;
    int dv0B=(int)rdv0B, dv1B=(int)rdv1B, dv2B=(int)rdv2B, dv3B=(int)rdv3B;

    hl A11A = split_ll((long long)iw0A*cu0A + (long long)iw1A*cu1A + (long long)iw2A*cu2A + (long long)iw3A*cu3A);
    hl A12A = split_ll((long long)iw0A*cv0A + (long long)iw1A*cv1A + (long long)iw2A*cv2A + (long long)iw3A*cv3A);
    hl A21A = split_ll((long long)iw0A*du0A + (long long)iw1A*du1A + (long long)iw2A*du2A + (long long)iw3A*du3A);
    hl A22A = split_ll((long long)iw0A*dv0A + (long long)iw1A*dv1A + (long long)iw2A*dv2A + (long long)iw3A*dv3A);
    hl A11B = split_ll((long long)iw0B*cu0B + (long long)iw1B*cu1B + (long long)iw2B*cu2B + (long long)iw3B*cu3B);
    hl A12B = split_ll((long long)iw0B*cv0B + (long long)iw1B*cv1B + (long long)iw2B*cv2B + (long long)iw3B*cv3B);
    hl A21B = split_ll((long long)iw0B*du0B + (long long)iw1B*du1B + (long long)iw2B*du2B + (long long)iw3B*du3B);
    hl A22B = split_ll((long long)iw0B*dv0B + (long long)iw1B*dv1B + (long long)iw2B*dv2B + (long long)iw3B*dv3B);

    // ---------- packed Kahan det2 / Cramer ----------
    u64 A11h = pk(A11A.h, A11B.h), A11l = pk(A11A.l, A11B.l);
    u64 A12h = pk(A12A.h, A12B.h), A12l = pk(A12A.l, A12B.l);
    u64 A21h = pk(A21A.h, A21B.h), A21l = pk(A21A.l, A21B.l);
    u64 A22h = pk(A22A.h, A22B.h), A22l = pk(A22A.l, A22B.l);

    u64 d0 = kdet2p(A11h, A22h, A12h, A21h);
    u64 dc = fma2(A11h, A22l,
             fma2(A11l, A22h,
             neg2(fma2(A12h, A21l, mul2(A12l, A21h)))));
    u64 det2 = add2(d0, dc);

    u64 n1 = add2(kdet2p(A22h, b1p, A12h, b2p),
                  fma2(A22l, b1p, neg2(mul2(A12l, b2p))));
    u64 n2 = add2(kdet2p(A11h, b2p, A21h, b1p),
                  fma2(A11l, b2p, neg2(mul2(A21l, b1p))));

    float det2A, det2B;
    upk(det2, det2A, det2B);
    u64 inv2 = pk(__frcp_rn(det2A), __frcp_rn(det2B));
    u64 z1p = mul2(n1, inv2);
    u64 z2p = mul2(n2, inv2);

    // ---------- packed g-RHS ----------
    u64 cu0p = pk(truncf(rcu0A), truncf(rcu0B)), cu1p = pk(truncf(rcu1A), truncf(rcu1B));
    u64 cu2p = pk(truncf(rcu2A), truncf(rcu2B)), cu3p = pk(truncf(rcu3A), truncf(rcu3B));
    u64 cv0p = pk(truncf(rcv0A), truncf(rcv0B)), cv1p = pk(truncf(rcv1A), truncf(rcv1B));
    u64 cv2p = pk(truncf(rcv2A), truncf(rcv2B)), cv3p = pk(truncf(rcv3A), truncf(rcv3B));
    u64 du0p = pk(truncf(rdu0A), truncf(rdu0B)), du1p = pk(truncf(rdu1A), truncf(rdu1B));
    u64 du2p = pk(truncf(rdu2A), truncf(rdu2B)), du3p = pk(truncf(rdu3A), truncf(rdu3B));
    u64 dv0p = pk(truncf(rdv0A), truncf(rdv0B)), dv1p = pk(truncf(rdv1A), truncf(rdv1B));
    u64 dv2p = pk(truncf(rdv2A), truncf(rdv2B)), dv3p = pk(truncf(rdv3A), truncf(rdv3B));

    u64 gx0 = fma2(du0p, z1p, fma2(dv0p, z2p, up0));
    u64 gx1 = fma2(du1p, z1p, fma2(dv1p, z2p, up1));
    u64 gx2 = fma2(du2p, z1p, fma2(dv2p, z2p, up2));
    u64 gx3 = fma2(du3p, z1p, fma2(dv3p, z2p, up3));
    u64 gy0 = fma2(cu0p, z1p, fma2(cv0p, z2p, vp0));
    u64 gy1 = fma2(cu1p, z1p, fma2(cv1p, z2p, vp1));
    u64 gy2 = fma2(cu2p, z1p, fma2(cv2p, z2p, vp2));
    u64 gy3 = fma2(cu3p, z1p, fma2(cv3p, z2p, vp3));

    float gx0A,gx0B,gx1A,gx1B,gx2A,gx2B,gx3A,gx3B;
    float gy0A,gy0B,gy1A,gy1B,gy2A,gy2B,gy3A,gy3B;
    upk(gx0,gx0A,gx0B); upk(gx1,gx1A,gx1B); upk(gx2,gx2A,gx2B); upk(gx3,gx3A,gx3B);
    upk(gy0,gy0A,gy0B); upk(gy1,gy1A,gy1B); upk(gy2,gy2A,gy2B); upk(gy3,gy3A,gy3B);
    float z1A,z1B,z2A,z2B;
    upk(z1p,z1A,z1B); upk(z2p,z2A,z2B);

    int tb = t & ~31;

    // ---- tail + store, system A ----
    tail_one(tu0A,tv0A,tu1A,tv1A,tu2A,tv2A,tu3A,tv3A,
             w0A,w1A,w2A,w3A,
             gx0A,gx1A,gx2A,gx3A, gy0A,gy1A,gy2A,gy3A,
             z1A,z2A, srow + lane * 9);
    __syncwarp();
    flush_tile(out, srow, (size_t)tb * 9, lane, (tb + 31 < T), (size_t)T * 9);
    __syncwarp();

    // ---- tail + store, system B ----
    tail_one(tu0B,tv0B,tu1B,tv1B,tu2B,tv2B,tu3B,tv3B,
             w0B,w1B,w2B,w3B,
             gx0B,gx1B,gx2B,gx3B, gy0B,gy1B,gy2B,gy3B,
             z1B,z2B, srow + lane * 9);
    __syncwarp();
    flush_tile(out, srow, ((size_t)tb + T) * 9, lane, (tb + T + 31 < B), (size_t)B * 9);
}

extern "C" void kernel_launch(void* const* d_in, const int* in_sizes, int n_in,
                              void* d_out, int out_size)
{
    const float* x  = (const float*)d_in[0];
    const float* xp = (const float*)d_in[1];
    float* out = (float*)d_out;
    int B = in_sizes[0] / 8;
    int Bo = out_size / 9;
    if (Bo < B) B = Bo;
    int T = (B + 1) / 2;                       // thread count; pair (t, t+T)
    dlt_kernel<<<(T + 127) / 128, 128>>>(x, xp, out, B, T);
}